// round 15
// baseline (speedup 1.0000x reference)
#include <cuda_runtime.h>
#include <cuda_fp16.h>
#include <math.h>

// Problem constants (fixed by setup_inputs)
#define NN   50000
#define MPAD 50048          // 391 * 128
#define EE   400000
#define ETOT (EE + NN)      // 450000
#define FIN  256
#define H1   4
#define D1   128
#define F1   512            // H1*D1
#define D2   64
#define NEG_SLOPE 0.2f
#define EPS 1e-16f
#define NB_SCAN 49          // ceil(NN/1024)

// ---------------- scratch (device globals; zero-initialized at load) ----------
// All GEMM outputs sized MPAD rows -> unconditional epilogue stores.
__device__ __half g_xl1h[(size_t)MPAD * F1];    // layer1 source transform, fp16
__device__ __half g_xr1h[(size_t)MPAD * F1];    // layer1 target transform, fp16
__device__ __half g_xl2h[(size_t)MPAD * D2];
__device__ __half g_xr2h[(size_t)MPAD * D2];
__device__ __half g_xh [(size_t)MPAD * FIN];    // fp16(x), pad rows zeroed
__device__ __half g_hh [(size_t)MPAD * F1];     // fp16(h), pad rows stay zero
__device__ __half g_w1 [1024 * FIN];            // [n,k] fused [Wl1|Wr1]^T fp16
__device__ __half g_w2 [128 * F1];              // [n,k] fused [Wl2|Wr2]^T fp16
__device__ int g_cnt[NN];
__device__ int g_off[NN + 1];
__device__ int g_cur[NN];
__device__ int g_csr[ETOT];
__device__ int g_bsum[64];
__device__ int g_is64;

// ---------------- helpers -----------------------------------------------------
__device__ __forceinline__ unsigned smem_u32(const void* p) {
    unsigned a;
    asm("{ .reg .u64 t; cvta.to.shared.u64 t, %1; cvt.u32.u64 %0, t; }"
        : "=r"(a) : "l"(p));
    return a;
}

__device__ __forceinline__ void ldmatrix_x4(unsigned& r0, unsigned& r1,
                                            unsigned& r2, unsigned& r3, unsigned addr) {
    asm volatile("ldmatrix.sync.aligned.m8n8.x4.shared.b16 {%0,%1,%2,%3}, [%4];"
                 : "=r"(r0), "=r"(r1), "=r"(r2), "=r"(r3) : "r"(addr));
}

__device__ __forceinline__ void mma_f16(float* c, const unsigned* a, const unsigned* b) {
    asm volatile(
        "mma.sync.aligned.m16n8k16.row.col.f32.f16.f16.f32 "
        "{%0,%1,%2,%3}, {%4,%5,%6,%7}, {%8,%9}, {%0,%1,%2,%3};"
        : "+f"(c[0]), "+f"(c[1]), "+f"(c[2]), "+f"(c[3])
        : "r"(a[0]), "r"(a[1]), "r"(a[2]), "r"(a[3]), "r"(b[0]), "r"(b[1]));
}

__device__ __forceinline__ void cp16(unsigned dst, const void* src) {
    asm volatile("cp.async.cg.shared.global [%0], [%1], 16;" :: "r"(dst), "l"(src));
}

__device__ __forceinline__ void store_pair(__half* p, float a, float b) {
    *reinterpret_cast<__half2*>(p) = __floats2half2_rn(a, b);
}

// ---------------- HMMA fp16 GEMM (3-stage cp.async pipeline) --------------------
// C[M, 2*HALF] = A[M,KC] @ B^T (B [2*HALF, KC] row-major, k-contig, fp16).
// Output col < HALF -> outL, else outR. Tile 128m x BNn, 8 warps (4m x 2n).
// M is MPAD (multiple of 128) -> no bounds checks anywhere.
#define BKK 64
#define SMSTRIDE 72   // 64 + 8 halves pad -> conflict-free ldmatrix
#define NSTAGE 3

constexpr int gemm_smem(int bn) { return (128 + bn) * SMSTRIDE * 2 * NSTAGE; }

template <int KC, int HALF, int BN>
__global__ void __launch_bounds__(256, 2)
gemm_hmma(const __half* __restrict__ A, const __half* __restrict__ B,
          __half* __restrict__ outL, __half* __restrict__ outR) {
    extern __shared__ __half sm[];
    constexpr int BUFA = 128 * SMSTRIDE;
    constexpr int BUFB = BN * SMSTRIDE;
    constexpr int STG = BUFA + BUFB;

    const int tid = threadIdx.x;
    const int lane = tid & 31;
    const int wid = tid >> 5;
    const int wm = wid & 3;
    const int wn = wid >> 2;
    const int bm = blockIdx.y * 128;
    const int bn = blockIdx.x * BN;
    constexpr int NKB = KC / BKK;
    constexpr int NPW = BN / 2;
    constexpr int NI = NPW / 8;
    constexpr int NP = NPW / 16;

    float acc[2][NI][4];
#pragma unroll
    for (int i = 0; i < 2; i++)
#pragma unroll
        for (int j = 0; j < NI; j++)
#pragma unroll
            for (int q = 0; q < 4; q++) acc[i][j][q] = 0.f;

    const int ld_row = tid >> 3;
    const int ld_seg = (tid & 7) * 8;

    auto load_stage = [&](int kb) {
        int st = kb % NSTAGE;
        __half* bufA = sm + st * STG;
        __half* bufB = bufA + BUFA;
#pragma unroll
        for (int rep = 0; rep < 4; rep++) {
            int row = ld_row + rep * 32;
            unsigned da = smem_u32(&bufA[row * SMSTRIDE + ld_seg]);
            cp16(da, A + (size_t)(bm + row) * KC + kb * BKK + ld_seg);
        }
#pragma unroll
        for (int rep = 0; rep < BN / 32; rep++) {
            int row = ld_row + rep * 32;
            unsigned db = smem_u32(&bufB[row * SMSTRIDE + ld_seg]);
            cp16(db, B + (size_t)(bn + row) * KC + kb * BKK + ld_seg);
        }
        asm volatile("cp.async.commit_group;" ::: "memory");
    };

    const int a_row = wm * 32 + (lane & 15);
    const int a_col = ((lane >> 4) << 3);
    const int b_row_base = wn * NPW + ((lane >> 4) << 3) + (lane & 7);
    const int b_col = (((lane >> 3) & 1) << 3);

    load_stage(0);
    if (NKB > 1) load_stage(1);
    for (int kb = 0; kb < NKB; kb++) {
        if (kb + 2 < NKB) {
            load_stage(kb + 2);
            asm volatile("cp.async.wait_group 2;" ::: "memory");
        } else if (kb + 1 < NKB) {
            asm volatile("cp.async.wait_group 1;" ::: "memory");
        } else {
            asm volatile("cp.async.wait_group 0;" ::: "memory");
        }
        __syncthreads();
        __half* sA = sm + (kb % NSTAGE) * STG;
        __half* sB = sA + BUFA;
#pragma unroll
        for (int ks = 0; ks < BKK / 16; ks++) {
            unsigned af[2][4];
#pragma unroll
            for (int mi = 0; mi < 2; mi++) {
                unsigned addr = smem_u32(&sA[(a_row + mi * 16) * SMSTRIDE + ks * 16 + a_col]);
                ldmatrix_x4(af[mi][0], af[mi][1], af[mi][2], af[mi][3], addr);
            }
            unsigned bf[NI][2];
#pragma unroll
            for (int np = 0; np < NP; np++) {
                unsigned addr = smem_u32(&sB[(b_row_base + np * 16) * SMSTRIDE + ks * 16 + b_col]);
                unsigned r0, r1, r2, r3;
                ldmatrix_x4(r0, r1, r2, r3, addr);
                bf[np * 2][0] = r0;  bf[np * 2][1] = r1;
                bf[np * 2 + 1][0] = r2;  bf[np * 2 + 1][1] = r3;
            }
#pragma unroll
            for (int mi = 0; mi < 2; mi++)
#pragma unroll
                for (int ni = 0; ni < NI; ni++)
                    mma_f16(acc[mi][ni], af[mi], bf[ni]);
        }
        __syncthreads();
    }

#pragma unroll
    for (int mi = 0; mi < 2; mi++) {
        int row0 = bm + wm * 32 + mi * 16 + (lane >> 2);
#pragma unroll
        for (int ni = 0; ni < NI; ni++) {
            int col = bn + wn * NPW + ni * 8 + (lane & 3) * 2;
            int ccol = (col < HALF) ? col : (col - HALF);
            __half* base = (col < HALF) ? outL : outR;
            store_pair(base + (size_t)row0 * HALF + ccol, acc[mi][ni][0], acc[mi][ni][1]);
            store_pair(base + (size_t)(row0 + 8) * HALF + ccol, acc[mi][ni][2], acc[mi][ni][3]);
        }
    }
}

// ---------------- fp16 conversions ---------------------------------------------
// xconv also zeroes g_cnt (its grid covers NN) -> one fewer launch.
__global__ void xconv_kernel(const float* __restrict__ src, __half* __restrict__ dst,
                             long long total) {
    long long i = (long long)blockIdx.x * blockDim.x + threadIdx.x;
    if (i >= total) return;
    if (i < NN) g_cnt[i] = 0;
    long long r = i / FIN;
    float v = (r < NN) ? src[i] : 0.f;
    dst[i] = __float2half_rn(v);
}

// Fused weight conversion for both layers in one launch.
// idx < 1024*256            : g_w1[n*256+k], n<512 -> Wl1[k*512+n], else Wr1
// idx >= 1024*256 (64K more): g_w2[n*512+k], n<64  -> Wl2[k*64+n],  else Wr2
#define W1TOT (1024 * 256)
#define W2TOT (128 * 512)
__global__ void wconv_kernel(const float* __restrict__ Wl1, const float* __restrict__ Wr1,
                             const float* __restrict__ Wl2, const float* __restrict__ Wr2) {
    int i = blockIdx.x * blockDim.x + threadIdx.x;
    if (i < W1TOT) {
        int n = i >> 8, k = i & 255;
        float v = (n < 512) ? Wl1[(size_t)k * 512 + n] : Wr1[(size_t)k * 512 + (n - 512)];
        g_w1[i] = __float2half_rn(v);
    } else if (i < W1TOT + W2TOT) {
        int j = i - W1TOT;
        int n = j >> 9, k = j & 511;
        float v = (n < 64) ? Wl2[(size_t)k * 64 + n] : Wr2[(size_t)k * 64 + (n - 64)];
        g_w2[j] = __float2half_rn(v);
    }
}

// ---------------- edge index handling ------------------------------------------
__device__ __forceinline__ void get_edge(const void* __restrict__ ei,
                                         int e, int& src, int& dst) {
    if (e >= EE) { src = dst = e - EE; return; }
    if (g_is64) {
        const long long* p = (const long long*)ei;
        src = (int)p[e];
        dst = (int)p[EE + e];
    } else {
        const int* p = (const int*)ei;
        src = p[e];
        dst = p[EE + e];
    }
}

__global__ void detect_dtype_kernel(const int* __restrict__ ei_as_i32) {
    int all_zero = 1;
    for (int i = 0; i < 16; i++)
        if (ei_as_i32[2 * i + 1] != 0) all_zero = 0;
    g_is64 = all_zero;
}

// ---------------- CSR build ------------------------------------------------------
__global__ void hist_kernel(const void* __restrict__ ei) {
    int e = blockIdx.x * blockDim.x + threadIdx.x;
    if (e >= ETOT) return;
    int src, dst;
    get_edge(ei, e, src, dst);
    atomicAdd(&g_cnt[dst], 1);
}

__global__ void scan_blocks_kernel() {
    __shared__ int wsum[32];
    int tid = threadIdx.x, lane = tid & 31, w = tid >> 5;
    int idx = blockIdx.x * 1024 + tid;
    int v = (idx < NN) ? g_cnt[idx] : 0;
    int s = v;
#pragma unroll
    for (int d = 1; d < 32; d <<= 1) {
        int t = __shfl_up_sync(0xFFFFFFFFu, s, d);
        if (lane >= d) s += t;
    }
    if (lane == 31) wsum[w] = s;
    __syncthreads();
    if (w == 0) {
        int ws = wsum[lane];
#pragma unroll
        for (int d = 1; d < 32; d <<= 1) {
            int t = __shfl_up_sync(0xFFFFFFFFu, ws, d);
            if (lane >= d) ws += t;
        }
        wsum[lane] = ws;
    }
    __syncthreads();
    int incl = (w ? wsum[w - 1] : 0) + s;
    if (idx < NN) g_off[idx] = incl - v;
    if (tid == 1023) g_bsum[blockIdx.x] = incl;
}

__global__ void scan_bsum_kernel() {
    if (threadIdx.x == 0) {
        int acc = 0;
        for (int b = 0; b < NB_SCAN; b++) {
            int t = g_bsum[b];
            g_bsum[b] = acc;
            acc += t;
        }
        g_off[NN] = acc;
    }
}

__global__ void scan_apply_kernel() {
    int idx = blockIdx.x * 1024 + threadIdx.x;
    if (idx < NN) {
        int o = g_off[idx] + g_bsum[blockIdx.x];
        g_off[idx] = o;
        g_cur[idx] = o;
    }
}

__global__ void scatter_kernel(const void* __restrict__ ei) {
    int e = blockIdx.x * blockDim.x + threadIdx.x;
    if (e >= ETOT) return;
    int src, dst;
    get_edge(ei, e, src, dst);
    int pos = atomicAdd(&g_cur[dst], 1);
    g_csr[pos] = src;
}

// ---------------- fused attention + aggregation, layer 1 (frozen R12 form) ------
__device__ __forceinline__ float edge_score(float4 a, float4 xr, float4 aw) {
    float s, v;
    v = a.x + xr.x; v = v > 0.f ? v : NEG_SLOPE * v; s  = v * aw.x;
    v = a.y + xr.y; v = v > 0.f ? v : NEG_SLOPE * v; s += v * aw.y;
    v = a.z + xr.z; v = v > 0.f ? v : NEG_SLOPE * v; s += v * aw.z;
    v = a.w + xr.w; v = v > 0.f ? v : NEG_SLOPE * v; s += v * aw.w;
    return s;
}

__device__ __forceinline__ float4 load_h4(const __half* p) {
    float2 raw = __ldg(reinterpret_cast<const float2*>(p));
    __half2 h0 = *reinterpret_cast<__half2*>(&raw.x);
    __half2 h1 = *reinterpret_cast<__half2*>(&raw.y);
    float2 a = __half22float2(h0);
    float2 b = __half22float2(h1);
    return make_float4(a.x, a.y, b.x, b.y);
}

__device__ __forceinline__ float2 load_h2(const __half* p) {
    unsigned raw = __ldg(reinterpret_cast<const unsigned*>(p));
    __half2 h = *reinterpret_cast<__half2*>(&raw);
    return __half22float2(h);
}

__global__ void att_agg1_kernel(const float* __restrict__ att1,
                                const float* __restrict__ b1) {
    int node = blockIdx.x;
    int warp = threadIdx.x >> 5;
    int lane = threadIdx.x & 31;
    int fofs = warp * D1 + lane * 4;

    float4 xr = load_h4(g_xr1h + (size_t)node * F1 + fofs);
    float4 aw = *reinterpret_cast<const float4*>(att1 + fofs);

    float4 acc = make_float4(0.f, 0.f, 0.f, 0.f);
    float den = 0.f;
    int s0 = g_off[node], s1 = g_off[node + 1];
    int i = s0;
    for (; i + 1 < s1; i += 2) {
        int src0 = __ldg(&g_csr[i]);
        int src1 = __ldg(&g_csr[i + 1]);
        float4 a0 = load_h4(g_xl1h + (size_t)src0 * F1 + fofs);
        float4 a1 = load_h4(g_xl1h + (size_t)src1 * F1 + fofs);
        float sc0 = edge_score(a0, xr, aw);
        float sc1 = edge_score(a1, xr, aw);
#pragma unroll
        for (int o = 16; o; o >>= 1) {
            sc0 += __shfl_xor_sync(0xFFFFFFFFu, sc0, o);
            sc1 += __shfl_xor_sync(0xFFFFFFFFu, sc1, o);
        }
        float e0 = __expf(sc0), e1 = __expf(sc1);
        acc.x += e0 * a0.x + e1 * a1.x;
        acc.y += e0 * a0.y + e1 * a1.y;
        acc.z += e0 * a0.z + e1 * a1.z;
        acc.w += e0 * a0.w + e1 * a1.w;
        den += e0 + e1;
    }
    if (i < s1) {
        int src = __ldg(&g_csr[i]);
        float4 a = load_h4(g_xl1h + (size_t)src * F1 + fofs);
        float sc = edge_score(a, xr, aw);
#pragma unroll
        for (int o = 16; o; o >>= 1) sc += __shfl_xor_sync(0xFFFFFFFFu, sc, o);
        float ex = __expf(sc);
        acc.x += ex * a.x;
        acc.y += ex * a.y;
        acc.z += ex * a.z;
        acc.w += ex * a.w;
        den += ex;
    }
    float inv = 1.f / (den + EPS);
    float4 bb = *reinterpret_cast<const float4*>(b1 + fofs);
    float o0, o1, o2, o3;
    o0 = acc.x * inv + bb.x; o0 = o0 > 0.f ? o0 : expm1f(o0);
    o1 = acc.y * inv + bb.y; o1 = o1 > 0.f ? o1 : expm1f(o1);
    o2 = acc.z * inv + bb.z; o2 = o2 > 0.f ? o2 : expm1f(o2);
    o3 = acc.w * inv + bb.w; o3 = o3 > 0.f ? o3 : expm1f(o3);

    __half* row = g_hh + (size_t)node * F1;
    *reinterpret_cast<__half2*>(row + fofs) = __floats2half2_rn(o0, o1);
    *reinterpret_cast<__half2*>(row + fofs + 2) = __floats2half2_rn(o2, o3);
}

// ---------------- fused attention + aggregation, layer 2 (frozen R12 form) ------
__device__ __forceinline__ float edge_score2(float2 a, float2 xr, float2 aw) {
    float s, v;
    v = a.x + xr.x; v = v > 0.f ? v : NEG_SLOPE * v; s  = v * aw.x;
    v = a.y + xr.y; v = v > 0.f ? v : NEG_SLOPE * v; s += v * aw.y;
    return s;
}

__global__ void att_agg2_kernel(const float* __restrict__ att2,
                                const float* __restrict__ b2,
                                float* __restrict__ out) {
    int node = blockIdx.x * (blockDim.x >> 5) + (threadIdx.x >> 5);
    if (node >= NN) return;
    int lane = threadIdx.x & 31;
    int fofs = lane * 2;

    float2 xr = load_h2(g_xr2h + (size_t)node * D2 + fofs);
    float2 aw = *reinterpret_cast<const float2*>(att2 + fofs);

    float2 acc = make_float2(0.f, 0.f);
    float den = 0.f;
    int s0 = g_off[node], s1 = g_off[node + 1];
    int i = s0;
    for (; i + 1 < s1; i += 2) {
        int src0 = __ldg(&g_csr[i]);
        int src1 = __ldg(&g_csr[i + 1]);
        float2 a0 = load_h2(g_xl2h + (size_t)src0 * D2 + fofs);
        float2 a1 = load_h2(g_xl2h + (size_t)src1 * D2 + fofs);
        float sc0 = edge_score2(a0, xr, aw);
        float sc1 = edge_score2(a1, xr, aw);
#pragma unroll
        for (int o = 16; o; o >>= 1) {
            sc0 += __shfl_xor_sync(0xFFFFFFFFu, sc0, o);
            sc1 += __shfl_xor_sync(0xFFFFFFFFu, sc1, o);
        }
        float e0 = __expf(sc0), e1 = __expf(sc1);
        acc.x += e0 * a0.x + e1 * a1.x;
        acc.y += e0 * a0.y + e1 * a1.y;
        den += e0 + e1;
    }
    if (i < s1) {
        int src = __ldg(&g_csr[i]);
        float2 a = load_h2(g_xl2h + (size_t)src * D2 + fofs);
        float sc = edge_score2(a, xr, aw);
#pragma unroll
        for (int o = 16; o; o >>= 1) sc += __shfl_xor_sync(0xFFFFFFFFu, sc, o);
        float ex = __expf(sc);
        acc.x += ex * a.x;
        acc.y += ex * a.y;
        den += ex;
    }
    float inv = 1.f / (den + EPS);
    float2 o;
    o.x = acc.x * inv + b2[fofs];
    o.y = acc.y * inv + b2[fofs + 1];
    *reinterpret_cast<float2*>(out + (size_t)node * D2 + fofs) = o;
}

// ---------------- launch -----------------------------------------------------------
extern "C" void kernel_launch(void* const* d_in, const int* in_sizes, int n_in,
                              void* d_out, int out_size) {
    const float* x    = (const float*)d_in[0];
    const void*  ei   = d_in[1];
    const float* Wl1  = (const float*)d_in[2];
    const float* Wr1  = (const float*)d_in[3];
    const float* att1 = (const float*)d_in[4];
    const float* b1   = (const float*)d_in[5];
    const float* Wl2  = (const float*)d_in[6];
    const float* Wr2  = (const float*)d_in[7];
    const float* att2 = (const float*)d_in[8];
    const float* b2   = (const float*)d_in[9];
    float* out = (float*)d_out;

    const int T = 256;
    __half *p_xl1h, *p_xr1h, *p_xl2h, *p_xr2h, *p_xh, *p_hh, *p_w1, *p_w2;
    cudaGetSymbolAddress((void**)&p_xl1h, g_xl1h);
    cudaGetSymbolAddress((void**)&p_xr1h, g_xr1h);
    cudaGetSymbolAddress((void**)&p_xl2h, g_xl2h);
    cudaGetSymbolAddress((void**)&p_xr2h, g_xr2h);
    cudaGetSymbolAddress((void**)&p_xh, g_xh);
    cudaGetSymbolAddress((void**)&p_hh, g_hh);
    cudaGetSymbolAddress((void**)&p_w1, g_w1);
    cudaGetSymbolAddress((void**)&p_w2, g_w2);

    cudaFuncSetAttribute((const void*)gemm_hmma<256, 512, 128>,
                         cudaFuncAttributeMaxDynamicSharedMemorySize, gemm_smem(128));
    cudaFuncSetAttribute((const void*)gemm_hmma<512, 64, 64>,
                         cudaFuncAttributeMaxDynamicSharedMemorySize, gemm_smem(64));

    // ---- dtype probe first, then conversions (xconv also zeroes g_cnt) ----
    detect_dtype_kernel<<<1, 1>>>((const int*)ei);
    {
        long long tot = (long long)MPAD * FIN;
        xconv_kernel<<<(unsigned)((tot + T - 1) / T), T>>>(x, p_xh, tot);
        wconv_kernel<<<(W1TOT + W2TOT + T - 1) / T, T>>>(Wl1, Wr1, Wl2, Wr2);
    }

    // ---- layer 1 GEMM: [MPAD,256] @ [1024,256]^T -> xl1, xr1 (fp16) ----
    {
        dim3 grid(8, MPAD / 128);
        gemm_hmma<256, 512, 128><<<grid, 256, gemm_smem(128)>>>(p_xh, p_w1, p_xl1h, p_xr1h);
    }

    // ---- CSR build ----
    hist_kernel<<<(ETOT + T - 1) / T, T>>>(ei);
    scan_blocks_kernel<<<NB_SCAN, 1024>>>();
    scan_bsum_kernel<<<1, 32>>>();
    scan_apply_kernel<<<NB_SCAN, 1024>>>();
    scatter_kernel<<<(ETOT + T - 1) / T, T>>>(ei);

    // ---- layer 1 fused attention + aggregation + bias + ELU -> fp16 h ----
    att_agg1_kernel<<<NN, 128>>>(att1, b1);

    // ---- layer 2 GEMM: [MPAD,512] @ [128,512]^T -> xl2, xr2 (fp16) ----
    {
        dim3 grid(2, MPAD / 128);
        gemm_hmma<512, 64, 64><<<grid, 256, gemm_smem(64)>>>(p_hh, p_w2, p_xl2h, p_xr2h);
    }

    // ---- layer 2 fused attention + aggregation ----
    att_agg2_kernel<<<(NN * 32 + T - 1) / T, T>>>(att2, b2, out);
}

// round 16
// speedup vs baseline: 1.0268x; 1.0268x over previous
#include <cuda_runtime.h>
#include <cuda_fp16.h>
#include <math.h>

// Problem constants (fixed by setup_inputs)
#define NN   50000
#define MPAD 50048          // 391 * 128
#define EE   400000
#define ETOT (EE + NN)      // 450000
#define FIN  256
#define H1   4
#define D1   128
#define F1   512            // H1*D1
#define D2   64
#define NEG_SLOPE 0.2f
#define EPS 1e-16f
#define NB_SCAN 49          // ceil(NN/1024)

// ---------------- scratch (device globals; zero-initialized at load) ----------
__device__ __half g_xl1h[(size_t)MPAD * F1];    // layer1 source transform, fp16
__device__ __half g_xr1h[(size_t)MPAD * F1];    // layer1 target transform, fp16
__device__ __half g_xl2h[(size_t)MPAD * D2];
__device__ __half g_xr2h[(size_t)MPAD * D2];
__device__ __half g_xh [(size_t)MPAD * FIN];    // fp16(x), pad rows zeroed
__device__ __half g_hh [(size_t)MPAD * F1];     // fp16(h), pad rows stay zero
__device__ __half g_w1 [1024 * FIN];            // [n,k] fused [Wl1|Wr1]^T fp16
__device__ __half g_w2 [128 * F1];              // [n,k] fused [Wl2|Wr2]^T fp16
__device__ int g_cnt[NN];
__device__ int g_off[NN + 1];
__device__ int g_cur[NN];
__device__ int g_csr[ETOT];
__device__ int g_bsum[64];
__device__ int g_is64;

// ---------------- helpers -----------------------------------------------------
__device__ __forceinline__ unsigned smem_u32(const void* p) {
    unsigned a;
    asm("{ .reg .u64 t; cvta.to.shared.u64 t, %1; cvt.u32.u64 %0, t; }"
        : "=r"(a) : "l"(p));
    return a;
}

__device__ __forceinline__ void ldmatrix_x4(unsigned& r0, unsigned& r1,
                                            unsigned& r2, unsigned& r3, unsigned addr) {
    asm volatile("ldmatrix.sync.aligned.m8n8.x4.shared.b16 {%0,%1,%2,%3}, [%4];"
                 : "=r"(r0), "=r"(r1), "=r"(r2), "=r"(r3) : "r"(addr));
}

__device__ __forceinline__ void mma_f16(float* c, const unsigned* a, const unsigned* b) {
    asm volatile(
        "mma.sync.aligned.m16n8k16.row.col.f32.f16.f16.f32 "
        "{%0,%1,%2,%3}, {%4,%5,%6,%7}, {%8,%9}, {%0,%1,%2,%3};"
        : "+f"(c[0]), "+f"(c[1]), "+f"(c[2]), "+f"(c[3])
        : "r"(a[0]), "r"(a[1]), "r"(a[2]), "r"(a[3]), "r"(b[0]), "r"(b[1]));
}

__device__ __forceinline__ void cp16(unsigned dst, const void* src) {
    asm volatile("cp.async.cg.shared.global [%0], [%1], 16;" :: "r"(dst), "l"(src));
}

__device__ __forceinline__ void store_pair(__half* p, float a, float b) {
    *reinterpret_cast<__half2*>(p) = __floats2half2_rn(a, b);
}

// ---------------- HMMA fp16 GEMM (3-stage cp.async pipeline) --------------------
#define BKK 64
#define SMSTRIDE 72   // 64 + 8 halves pad -> conflict-free ldmatrix
#define NSTAGE 3

constexpr int gemm_smem(int bn) { return (128 + bn) * SMSTRIDE * 2 * NSTAGE; }

template <int KC, int HALF, int BN>
__global__ void __launch_bounds__(256, 2)
gemm_hmma(const __half* __restrict__ A, const __half* __restrict__ B,
          __half* __restrict__ outL, __half* __restrict__ outR) {
    extern __shared__ __half sm[];
    constexpr int BUFA = 128 * SMSTRIDE;
    constexpr int BUFB = BN * SMSTRIDE;
    constexpr int STG = BUFA + BUFB;

    const int tid = threadIdx.x;
    const int lane = tid & 31;
    const int wid = tid >> 5;
    const int wm = wid & 3;
    const int wn = wid >> 2;
    const int bm = blockIdx.y * 128;
    const int bn = blockIdx.x * BN;
    constexpr int NKB = KC / BKK;
    constexpr int NPW = BN / 2;
    constexpr int NI = NPW / 8;
    constexpr int NP = NPW / 16;

    float acc[2][NI][4];
#pragma unroll
    for (int i = 0; i < 2; i++)
#pragma unroll
        for (int j = 0; j < NI; j++)
#pragma unroll
            for (int q = 0; q < 4; q++) acc[i][j][q] = 0.f;

    const int ld_row = tid >> 3;
    const int ld_seg = (tid & 7) * 8;

    auto load_stage = [&](int kb) {
        int st = kb % NSTAGE;
        __half* bufA = sm + st * STG;
        __half* bufB = bufA + BUFA;
#pragma unroll
        for (int rep = 0; rep < 4; rep++) {
            int row = ld_row + rep * 32;
            unsigned da = smem_u32(&bufA[row * SMSTRIDE + ld_seg]);
            cp16(da, A + (size_t)(bm + row) * KC + kb * BKK + ld_seg);
        }
#pragma unroll
        for (int rep = 0; rep < BN / 32; rep++) {
            int row = ld_row + rep * 32;
            unsigned db = smem_u32(&bufB[row * SMSTRIDE + ld_seg]);
            cp16(db, B + (size_t)(bn + row) * KC + kb * BKK + ld_seg);
        }
        asm volatile("cp.async.commit_group;" ::: "memory");
    };

    const int a_row = wm * 32 + (lane & 15);
    const int a_col = ((lane >> 4) << 3);
    const int b_row_base = wn * NPW + ((lane >> 4) << 3) + (lane & 7);
    const int b_col = (((lane >> 3) & 1) << 3);

    load_stage(0);
    if (NKB > 1) load_stage(1);
    for (int kb = 0; kb < NKB; kb++) {
        if (kb + 2 < NKB) {
            load_stage(kb + 2);
            asm volatile("cp.async.wait_group 2;" ::: "memory");
        } else if (kb + 1 < NKB) {
            asm volatile("cp.async.wait_group 1;" ::: "memory");
        } else {
            asm volatile("cp.async.wait_group 0;" ::: "memory");
        }
        __syncthreads();
        __half* sA = sm + (kb % NSTAGE) * STG;
        __half* sB = sA + BUFA;
#pragma unroll
        for (int ks = 0; ks < BKK / 16; ks++) {
            unsigned af[2][4];
#pragma unroll
            for (int mi = 0; mi < 2; mi++) {
                unsigned addr = smem_u32(&sA[(a_row + mi * 16) * SMSTRIDE + ks * 16 + a_col]);
                ldmatrix_x4(af[mi][0], af[mi][1], af[mi][2], af[mi][3], addr);
            }
            unsigned bf[NI][2];
#pragma unroll
            for (int np = 0; np < NP; np++) {
                unsigned addr = smem_u32(&sB[(b_row_base + np * 16) * SMSTRIDE + ks * 16 + b_col]);
                unsigned r0, r1, r2, r3;
                ldmatrix_x4(r0, r1, r2, r3, addr);
                bf[np * 2][0] = r0;  bf[np * 2][1] = r1;
                bf[np * 2 + 1][0] = r2;  bf[np * 2 + 1][1] = r3;
            }
#pragma unroll
            for (int mi = 0; mi < 2; mi++)
#pragma unroll
                for (int ni = 0; ni < NI; ni++)
                    mma_f16(acc[mi][ni], af[mi], bf[ni]);
        }
        __syncthreads();
    }

#pragma unroll
    for (int mi = 0; mi < 2; mi++) {
        int row0 = bm + wm * 32 + mi * 16 + (lane >> 2);
#pragma unroll
        for (int ni = 0; ni < NI; ni++) {
            int col = bn + wn * NPW + ni * 8 + (lane & 3) * 2;
            int ccol = (col < HALF) ? col : (col - HALF);
            __half* base = (col < HALF) ? outL : outR;
            store_pair(base + (size_t)row0 * HALF + ccol, acc[mi][ni][0], acc[mi][ni][1]);
            store_pair(base + (size_t)(row0 + 8) * HALF + ccol, acc[mi][ni][2], acc[mi][ni][3]);
        }
    }
}

// ---------------- fp16 conversions ---------------------------------------------
__global__ void xconv_kernel(const float* __restrict__ src, __half* __restrict__ dst,
                             long long total) {
    long long i = (long long)blockIdx.x * blockDim.x + threadIdx.x;
    if (i >= total) return;
    long long r = i / FIN;
    float v = (r < NN) ? src[i] : 0.f;
    dst[i] = __float2half_rn(v);
}

#define W1TOT (1024 * 256)
#define W2TOT (128 * 512)
__global__ void wconv_kernel(const float* __restrict__ Wl1, const float* __restrict__ Wr1,
                             const float* __restrict__ Wl2, const float* __restrict__ Wr2) {
    int i = blockIdx.x * blockDim.x + threadIdx.x;
    if (i < W1TOT) {
        int n = i >> 8, k = i & 255;
        float v = (n < 512) ? Wl1[(size_t)k * 512 + n] : Wr1[(size_t)k * 512 + (n - 512)];
        g_w1[i] = __float2half_rn(v);
    } else if (i < W1TOT + W2TOT) {
        int j = i - W1TOT;
        int n = j >> 9, k = j & 511;
        float v = (n < 64) ? Wl2[(size_t)k * 64 + n] : Wr2[(size_t)k * 64 + (n - 64)];
        g_w2[j] = __float2half_rn(v);
    }
}

// ---------------- edge index handling ------------------------------------------
__device__ __forceinline__ void get_edge(const void* __restrict__ ei,
                                         int e, int& src, int& dst) {
    if (e >= EE) { src = dst = e - EE; return; }
    if (g_is64) {
        const long long* p = (const long long*)ei;
        src = (int)p[e];
        dst = (int)p[EE + e];
    } else {
        const int* p = (const int*)ei;
        src = p[e];
        dst = p[EE + e];
    }
}

// detect dtype + zero g_cnt in one kernel (runs on CSR stream)
__global__ void csr_init_kernel(const int* __restrict__ ei_as_i32) {
    int i = blockIdx.x * blockDim.x + threadIdx.x;
    if (i == 0) {
        int all_zero = 1;
        for (int t = 0; t < 16; t++)
            if (ei_as_i32[2 * t + 1] != 0) all_zero = 0;
        g_is64 = all_zero;
    }
    if (i < NN) g_cnt[i] = 0;
}

// ---------------- CSR build ------------------------------------------------------
__global__ void hist_kernel(const void* __restrict__ ei) {
    int e = blockIdx.x * blockDim.x + threadIdx.x;
    if (e >= ETOT) return;
    int src, dst;
    get_edge(ei, e, src, dst);
    atomicAdd(&g_cnt[dst], 1);
}

__global__ void scan_blocks_kernel() {
    __shared__ int wsum[32];
    int tid = threadIdx.x, lane = tid & 31, w = tid >> 5;
    int idx = blockIdx.x * 1024 + tid;
    int v = (idx < NN) ? g_cnt[idx] : 0;
    int s = v;
#pragma unroll
    for (int d = 1; d < 32; d <<= 1) {
        int t = __shfl_up_sync(0xFFFFFFFFu, s, d);
        if (lane >= d) s += t;
    }
    if (lane == 31) wsum[w] = s;
    __syncthreads();
    if (w == 0) {
        int ws = wsum[lane];
#pragma unroll
        for (int d = 1; d < 32; d <<= 1) {
            int t = __shfl_up_sync(0xFFFFFFFFu, ws, d);
            if (lane >= d) ws += t;
        }
        wsum[lane] = ws;
    }
    __syncthreads();
    int incl = (w ? wsum[w - 1] : 0) + s;
    if (idx < NN) g_off[idx] = incl - v;
    if (tid == 1023) g_bsum[blockIdx.x] = incl;
}

__global__ void scan_bsum_kernel() {
    if (threadIdx.x == 0) {
        int acc = 0;
        for (int b = 0; b < NB_SCAN; b++) {
            int t = g_bsum[b];
            g_bsum[b] = acc;
            acc += t;
        }
        g_off[NN] = acc;
    }
}

__global__ void scan_apply_kernel() {
    int idx = blockIdx.x * 1024 + threadIdx.x;
    if (idx < NN) {
        int o = g_off[idx] + g_bsum[blockIdx.x];
        g_off[idx] = o;
        g_cur[idx] = o;
    }
}

__global__ void scatter_kernel(const void* __restrict__ ei) {
    int e = blockIdx.x * blockDim.x + threadIdx.x;
    if (e >= ETOT) return;
    int src, dst;
    get_edge(ei, e, src, dst);
    int pos = atomicAdd(&g_cur[dst], 1);
    g_csr[pos] = src;
}

// ---------------- fused attention + aggregation, layer 1 (frozen R12 form) ------
__device__ __forceinline__ float edge_score(float4 a, float4 xr, float4 aw) {
    float s, v;
    v = a.x + xr.x; v = v > 0.f ? v : NEG_SLOPE * v; s  = v * aw.x;
    v = a.y + xr.y; v = v > 0.f ? v : NEG_SLOPE * v; s += v * aw.y;
    v = a.z + xr.z; v = v > 0.f ? v : NEG_SLOPE * v; s += v * aw.z;
    v = a.w + xr.w; v = v > 0.f ? v : NEG_SLOPE * v; s += v * aw.w;
    return s;
}

__device__ __forceinline__ float4 load_h4(const __half* p) {
    float2 raw = __ldg(reinterpret_cast<const float2*>(p));
    __half2 h0 = *reinterpret_cast<__half2*>(&raw.x);
    __half2 h1 = *reinterpret_cast<__half2*>(&raw.y);
    float2 a = __half22float2(h0);
    float2 b = __half22float2(h1);
    return make_float4(a.x, a.y, b.x, b.y);
}

__device__ __forceinline__ float2 load_h2(const __half* p) {
    unsigned raw = __ldg(reinterpret_cast<const unsigned*>(p));
    __half2 h = *reinterpret_cast<__half2*>(&raw);
    return __half22float2(h);
}

__global__ void att_agg1_kernel(const float* __restrict__ att1,
                                const float* __restrict__ b1) {
    int node = blockIdx.x;
    int warp = threadIdx.x >> 5;
    int lane = threadIdx.x & 31;
    int fofs = warp * D1 + lane * 4;

    float4 xr = load_h4(g_xr1h + (size_t)node * F1 + fofs);
    float4 aw = *reinterpret_cast<const float4*>(att1 + fofs);

    float4 acc = make_float4(0.f, 0.f, 0.f, 0.f);
    float den = 0.f;
    int s0 = g_off[node], s1 = g_off[node + 1];
    int i = s0;
    for (; i + 1 < s1; i += 2) {
        int src0 = __ldg(&g_csr[i]);
        int src1 = __ldg(&g_csr[i + 1]);
        float4 a0 = load_h4(g_xl1h + (size_t)src0 * F1 + fofs);
        float4 a1 = load_h4(g_xl1h + (size_t)src1 * F1 + fofs);
        float sc0 = edge_score(a0, xr, aw);
        float sc1 = edge_score(a1, xr, aw);
#pragma unroll
        for (int o = 16; o; o >>= 1) {
            sc0 += __shfl_xor_sync(0xFFFFFFFFu, sc0, o);
            sc1 += __shfl_xor_sync(0xFFFFFFFFu, sc1, o);
        }
        float e0 = __expf(sc0), e1 = __expf(sc1);
        acc.x += e0 * a0.x + e1 * a1.x;
        acc.y += e0 * a0.y + e1 * a1.y;
        acc.z += e0 * a0.z + e1 * a1.z;
        acc.w += e0 * a0.w + e1 * a1.w;
        den += e0 + e1;
    }
    if (i < s1) {
        int src = __ldg(&g_csr[i]);
        float4 a = load_h4(g_xl1h + (size_t)src * F1 + fofs);
        float sc = edge_score(a, xr, aw);
#pragma unroll
        for (int o = 16; o; o >>= 1) sc += __shfl_xor_sync(0xFFFFFFFFu, sc, o);
        float ex = __expf(sc);
        acc.x += ex * a.x;
        acc.y += ex * a.y;
        acc.z += ex * a.z;
        acc.w += ex * a.w;
        den += ex;
    }
    float inv = 1.f / (den + EPS);
    float4 bb = *reinterpret_cast<const float4*>(b1 + fofs);
    float o0, o1, o2, o3;
    o0 = acc.x * inv + bb.x; o0 = o0 > 0.f ? o0 : expm1f(o0);
    o1 = acc.y * inv + bb.y; o1 = o1 > 0.f ? o1 : expm1f(o1);
    o2 = acc.z * inv + bb.z; o2 = o2 > 0.f ? o2 : expm1f(o2);
    o3 = acc.w * inv + bb.w; o3 = o3 > 0.f ? o3 : expm1f(o3);

    __half* row = g_hh + (size_t)node * F1;
    *reinterpret_cast<__half2*>(row + fofs) = __floats2half2_rn(o0, o1);
    *reinterpret_cast<__half2*>(row + fofs + 2) = __floats2half2_rn(o2, o3);
}

// ---------------- fused attention + aggregation, layer 2 (frozen R12 form) ------
__device__ __forceinline__ float edge_score2(float2 a, float2 xr, float2 aw) {
    float s, v;
    v = a.x + xr.x; v = v > 0.f ? v : NEG_SLOPE * v; s  = v * aw.x;
    v = a.y + xr.y; v = v > 0.f ? v : NEG_SLOPE * v; s += v * aw.y;
    return s;
}

__global__ void att_agg2_kernel(const float* __restrict__ att2,
                                const float* __restrict__ b2,
                                float* __restrict__ out) {
    int node = blockIdx.x * (blockDim.x >> 5) + (threadIdx.x >> 5);
    if (node >= NN) return;
    int lane = threadIdx.x & 31;
    int fofs = lane * 2;

    float2 xr = load_h2(g_xr2h + (size_t)node * D2 + fofs);
    float2 aw = *reinterpret_cast<const float2*>(att2 + fofs);

    float2 acc = make_float2(0.f, 0.f);
    float den = 0.f;
    int s0 = g_off[node], s1 = g_off[node + 1];
    int i = s0;
    for (; i + 1 < s1; i += 2) {
        int src0 = __ldg(&g_csr[i]);
        int src1 = __ldg(&g_csr[i + 1]);
        float2 a0 = load_h2(g_xl2h + (size_t)src0 * D2 + fofs);
        float2 a1 = load_h2(g_xl2h + (size_t)src1 * D2 + fofs);
        float sc0 = edge_score2(a0, xr, aw);
        float sc1 = edge_score2(a1, xr, aw);
#pragma unroll
        for (int o = 16; o; o >>= 1) {
            sc0 += __shfl_xor_sync(0xFFFFFFFFu, sc0, o);
            sc1 += __shfl_xor_sync(0xFFFFFFFFu, sc1, o);
        }
        float e0 = __expf(sc0), e1 = __expf(sc1);
        acc.x += e0 * a0.x + e1 * a1.x;
        acc.y += e0 * a0.y + e1 * a1.y;
        den += e0 + e1;
    }
    if (i < s1) {
        int src = __ldg(&g_csr[i]);
        float2 a = load_h2(g_xl2h + (size_t)src * D2 + fofs);
        float sc = edge_score2(a, xr, aw);
#pragma unroll
        for (int o = 16; o; o >>= 1) sc += __shfl_xor_sync(0xFFFFFFFFu, sc, o);
        float ex = __expf(sc);
        acc.x += ex * a.x;
        acc.y += ex * a.y;
        den += ex;
    }
    float inv = 1.f / (den + EPS);
    float2 o;
    o.x = acc.x * inv + b2[fofs];
    o.y = acc.y * inv + b2[fofs + 1];
    *reinterpret_cast<float2*>(out + (size_t)node * D2 + fofs) = o;
}

// ---------------- launch -----------------------------------------------------------
extern "C" void kernel_launch(void* const* d_in, const int* in_sizes, int n_in,
                              void* d_out, int out_size) {
    const float* x    = (const float*)d_in[0];
    const void*  ei   = d_in[1];
    const float* Wl1  = (const float*)d_in[2];
    const float* Wr1  = (const float*)d_in[3];
    const float* att1 = (const float*)d_in[4];
    const float* b1   = (const float*)d_in[5];
    const float* Wl2  = (const float*)d_in[6];
    const float* Wr2  = (const float*)d_in[7];
    const float* att2 = (const float*)d_in[8];
    const float* b2   = (const float*)d_in[9];
    float* out = (float*)d_out;

    const int T = 256;
    __half *p_xl1h, *p_xr1h, *p_xl2h, *p_xr2h, *p_xh, *p_hh, *p_w1, *p_w2;
    cudaGetSymbolAddress((void**)&p_xl1h, g_xl1h);
    cudaGetSymbolAddress((void**)&p_xr1h, g_xr1h);
    cudaGetSymbolAddress((void**)&p_xl2h, g_xl2h);
    cudaGetSymbolAddress((void**)&p_xr2h, g_xr2h);
    cudaGetSymbolAddress((void**)&p_xh, g_xh);
    cudaGetSymbolAddress((void**)&p_hh, g_hh);
    cudaGetSymbolAddress((void**)&p_w1, g_w1);
    cudaGetSymbolAddress((void**)&p_w2, g_w2);

    cudaFuncSetAttribute((const void*)gemm_hmma<256, 512, 128>,
                         cudaFuncAttributeMaxDynamicSharedMemorySize, gemm_smem(128));
    cudaFuncSetAttribute((const void*)gemm_hmma<512, 64, 64>,
                         cudaFuncAttributeMaxDynamicSharedMemorySize, gemm_smem(64));

    // One-time handle setup (outside capture on the first/correctness call;
    // reused under graph capture — per-call work is identical).
    static cudaStream_t s_csr = nullptr;
    static cudaEvent_t ev_fork = nullptr, ev_join = nullptr;
    if (s_csr == nullptr) {
        cudaStreamCreateWithFlags(&s_csr, cudaStreamNonBlocking);
        cudaEventCreateWithFlags(&ev_fork, cudaEventDisableTiming);
        cudaEventCreateWithFlags(&ev_join, cudaEventDisableTiming);
    }

    // ---- fork: CSR build on side stream, conversions+GEMM1 on main stream ----
    cudaEventRecord(ev_fork, 0);
    cudaStreamWaitEvent(s_csr, ev_fork, 0);

    // side stream: dtype probe + cnt zero, hist, scan, scatter
    csr_init_kernel<<<(NN + T - 1) / T, T, 0, s_csr>>>((const int*)ei);
    hist_kernel<<<(ETOT + T - 1) / T, T, 0, s_csr>>>(ei);
    scan_blocks_kernel<<<NB_SCAN, 1024, 0, s_csr>>>();
    scan_bsum_kernel<<<1, 32, 0, s_csr>>>();
    scan_apply_kernel<<<NB_SCAN, 1024, 0, s_csr>>>();
    scatter_kernel<<<(ETOT + T - 1) / T, T, 0, s_csr>>>(ei);
    cudaEventRecord(ev_join, s_csr);

    // main stream: conversions + layer 1 GEMM
    {
        long long tot = (long long)MPAD * FIN;
        xconv_kernel<<<(unsigned)((tot + T - 1) / T), T>>>(x, p_xh, tot);
        wconv_kernel<<<(W1TOT + W2TOT + T - 1) / T, T>>>(Wl1, Wr1, Wl2, Wr2);
    }
    {
        dim3 grid(8, MPAD / 128);
        gemm_hmma<256, 512, 128><<<grid, 256, gemm_smem(128)>>>(p_xh, p_w1, p_xl1h, p_xr1h);
    }

    // ---- join: att_agg1 needs both GEMM1 outputs and the CSR ----
    cudaStreamWaitEvent(0, ev_join, 0);

    att_agg1_kernel<<<NN, 128>>>(att1, b1);

    // ---- layer 2 GEMM: [MPAD,512] @ [128,512]^T -> xl2, xr2 (fp16) ----
    {
        dim3 grid(2, MPAD / 128);
        gemm_hmma<512, 64, 64><<<grid, 256, gemm_smem(64)>>>(p_hh, p_w2, p_xl2h, p_xr2h);
    }

    // ---- layer 2 fused attention + aggregation ----
    att_agg2_kernel<<<(NN * 32 + T - 1) / T, T>>>(att2, b2, out);
}